// round 16
// baseline (speedup 1.0000x reference)
#include <cuda_runtime.h>
#include <math.h>

#define Tt 64
#define Bb 256
#define Nn 256
#define Mm 128
#define Hh 1024
#define Ii 128
#define EPSf 1e-8f
#define NCTA 256
#define NTHR 512

typedef unsigned long long ull;

#define SBUF 8448      // floats (dynamic)
#define SAS1 260       // P1 A row stride
#define SAS2 516       // P2 A row stride

// ---------------- persistent device scratch ----------------
__device__ __align__(16) float g_mem[Bb*Nn*Mm];   // 33.5 MB, L2-resident
__device__ __align__(16) float g_ht [Bb*Hh];
__device__ __align__(16) float g_k  [2*Bb*Mm];
__device__ __align__(16) float g_e  [Bb*Mm];
__device__ __align__(16) float g_a  [Bb*Mm];
__device__ __align__(16) float g_rd [Bb*Mm];
__device__ __align__(16) float g_Wot[Ii*Mm];      // Wo^T [col][m]
__device__ unsigned g_cnt[8*32];
__device__ unsigned g_gen[8*32];

// ---------------- f32x2 packed math ----------------
__device__ __forceinline__ ull pk2(float a){
    ull r; asm("mov.b64 %0,{%1,%1};" : "=l"(r) : "f"(a)); return r;
}
__device__ __forceinline__ void f2fma(ull& c, ull a, ull b){
    asm("fma.rn.f32x2 %0,%1,%2,%0;" : "+l"(c) : "l"(a), "l"(b));
}
__device__ __forceinline__ ull ad2(ull a, ull b){
    ull r; asm("add.rn.f32x2 %0,%1,%2;" : "=l"(r) : "l"(a), "l"(b)); return r;
}
__device__ __forceinline__ float2 up2(ull v){
    float2 f; asm("mov.b64 {%0,%1},%2;" : "=f"(f.x), "=f"(f.y) : "l"(v)); return f;
}

// ---------------- group barrier (32 CTAs; all deps group-local) ----------------
__device__ __forceinline__ void gbar(int grp){
    __threadfence();
    __syncthreads();
    if (threadIdx.x == 0){
        volatile unsigned* genp = &g_gen[grp*32];
        unsigned cur = *genp;
        if (atomicAdd(&g_cnt[grp*32], 1u) == 31u){
            g_cnt[grp*32] = 0u;
            __threadfence();
            *genp = cur + 1u;
        } else {
            while (*genp == cur) { __nanosleep(32); }
        }
        __threadfence();
    }
    __syncthreads();
}

// ---------------- full-block reductions (512 thr), init only ----------------
__device__ __forceinline__ float bredSum(float v, float* s_red){
    int lane = threadIdx.x & 31, wid = threadIdx.x >> 5;
    #pragma unroll
    for (int off = 16; off; off >>= 1) v += __shfl_xor_sync(0xffffffffu, v, off);
    if (lane == 0) s_red[wid] = v;
    __syncthreads();
    if (threadIdx.x == 0){
        float s = 0.f;
        #pragma unroll
        for (int j = 0; j < 16; j++) s += s_red[j];
        s_red[32] = s;
    }
    __syncthreads();
    return s_red[32];
}
__device__ __forceinline__ float bredMax(float v, float* s_red){
    int lane = threadIdx.x & 31, wid = threadIdx.x >> 5;
    #pragma unroll
    for (int off = 16; off; off >>= 1) v = fmaxf(v, __shfl_xor_sync(0xffffffffu, v, off));
    if (lane == 0) s_red[wid] = v;
    __syncthreads();
    if (threadIdx.x == 0){
        float s = -3.4e38f;
        #pragma unroll
        for (int j = 0; j < 16; j++) s = fmaxf(s, s_red[j]);
        s_red[32] = s;
    }
    __syncthreads();
    return s_red[32];
}

// ---------------- half-block reductions (256 thr per half, parallel heads) ----------------
__device__ __forceinline__ float hredSum(float v, float* s_red){
    int tid = threadIdx.x;
    int lane = tid & 31, wid = tid >> 5, half = tid >> 8;
    #pragma unroll
    for (int off = 16; off; off >>= 1) v += __shfl_xor_sync(0xffffffffu, v, off);
    if (lane == 0) s_red[wid] = v;
    __syncthreads();
    if ((tid & 255) == 0){
        float s = 0.f;
        #pragma unroll
        for (int j = 0; j < 8; j++) s += s_red[(half<<3) + j];
        s_red[32 + half] = s;
    }
    __syncthreads();
    return s_red[32 + half];
}
__device__ __forceinline__ float hredMax(float v, float* s_red){
    int tid = threadIdx.x;
    int lane = tid & 31, wid = tid >> 5, half = tid >> 8;
    #pragma unroll
    for (int off = 16; off; off >>= 1) v = fmaxf(v, __shfl_xor_sync(0xffffffffu, v, off));
    if (lane == 0) s_red[wid] = v;
    __syncthreads();
    if ((tid & 255) == 0){
        float s = -3.4e38f;
        #pragma unroll
        for (int j = 0; j < 8; j++) s = fmaxf(s, s_red[(half<<3) + j]);
        s_red[32 + half] = s;
    }
    __syncthreads();
    return s_red[32 + half];
}

__device__ __forceinline__ float softplusf(float x){
    return fmaxf(x, 0.f) + log1pf(expf(-fabsf(x)));
}
__device__ __forceinline__ float sigmoidf_(float x){
    return 1.f / (1.f + expf(-x));
}

// ---------------- the persistent NTM kernel ----------------
__global__ void __launch_bounds__(NTHR, 2) ntm_kernel(
    const float* __restrict__ x,
    const float* __restrict__ Wc,   const float* __restrict__ bc,
    const float* __restrict__ Wk,   const float* __restrict__ bk,
    const float* __restrict__ Wb,   const float* __restrict__ bb,
    const float* __restrict__ Wg,   const float* __restrict__ bg,
    const float* __restrict__ Ws,   const float* __restrict__ bs,
    const float* __restrict__ Wgam, const float* __restrict__ bgam,
    const float* __restrict__ We,   const float* __restrict__ be,
    const float* __restrict__ Wa,   const float* __restrict__ ba,
    const float* __restrict__ Wo,   const float* __restrict__ bo,
    const float* __restrict__ memory0,
    const float* __restrict__ ww0,  const float* __restrict__ rw0,
    const float* __restrict__ read0,
    float* __restrict__ out)
{
    extern __shared__ __align__(16) float s_buf[];

    __shared__ float s_ww[Nn];
    __shared__ float s_rw[Nn];
    __shared__ float s_nrm[Nn];     // inverse memory row norms (persist across t)
    __shared__ float s_red[40];
    __shared__ float s_sm[16];

    const int tid  = threadIdx.x;
    const int cta  = blockIdx.x;
    const int b    = cta;
    const int grp  = cta >> 5;
    const int wid  = tid >> 5, lane = tid & 31;

    // ---- P1: 8 RB(32 rows) x 32 CB(32 cols) over [256,1024], k=256, k-split 4 ----
    const int RB1 = cta >> 5, CB1 = cta & 31;
    const int ks1 = tid >> 7, t7 = tid & 127;
    const int rp1 = t7 >> 3, cq1 = t7 & 7;
    const int c4g1 = CB1*8 + cq1;
    // ---- P2: 16 RB(16 rows) x 16 CB(32 cols) over [256,512], k=1024, k-split 8 ----
    const int RB2 = cta >> 4, CB2 = cta & 15;
    const int seg = CB2 >> 2;
    const int g4 = tid >> 6, t6 = tid & 63;
    const int rp2 = t6 >> 3, cq2 = t6 & 7;
    const int c4s = (CB2 & 3)*8 + cq2;
    const float *Wp2, *bp2; float *op2;
    if      (seg == 0){ Wp2 = Wk;          bp2 = bk;      op2 = g_k; }
    else if (seg == 1){ Wp2 = Wk + Hh*Mm;  bp2 = bk + Mm; op2 = g_k + Bb*Mm; }
    else if (seg == 2){ Wp2 = We;          bp2 = be;      op2 = g_e; }
    else              { Wp2 = Wa;          bp2 = ba;      op2 = g_a; }

    // P3/P4 scratch carve inside s_buf
    float*  s_kw  = s_buf;                 // 128
    float*  s_kr  = s_buf + 128;           // 128
    float*  s_e   = s_buf + 256;           // 128
    float*  s_a   = s_buf + 384;           // 128
    float*  s_zw  = s_buf + 512;           // 256
    float*  s_zr  = s_buf + 768;           // 256
    float*  s_tmp = s_buf + 1024;          // 512 (two head buffers)
    float4* s_prd = (float4*)(s_buf + 1536); // 512 f4 -> up to 3584
    float*  s_ht  = s_buf + 4096;          // 1024 floats (ht[b] stage for smalls)

    // ---------------- init ----------------
    {
        {
            int col = CB1*4 + (tid >> 7), m = tid & 127;
            g_Wot[col*Mm + m] = Wo[m*Ii + col];
        }
        float4*       md = ((float4*)g_mem) + b * (Nn*Mm/4);
        const float4* ms = (const float4*)memory0;
        for (int i = tid; i < Nn*Mm/4; i += NTHR) md[i] = ms[i];
        if (tid < Mm) __stcg(&g_rd[b*Mm + tid], read0[tid]);
        __syncthreads();
        // initial inverse row norms (16 warps x 16 rows)
        for (int j = 0; j < 16; j++){
            int n = wid*16 + j;
            float4 mv = __ldcg((const float4*)&md[n*32 + lane]);
            float nn = mv.x*mv.x + mv.y*mv.y + mv.z*mv.z + mv.w*mv.w;
            #pragma unroll
            for (int off = 16; off; off >>= 1) nn += __shfl_xor_sync(0xffffffffu, nn, off);
            if (lane == 0) s_nrm[n] = 1.f / fmaxf(sqrtf(nn), EPSf);
        }
        float v  = (tid < Nn) ? ww0[tid] : -3.4e38f;
        float mx = bredMax(v, s_red);
        float e  = (tid < Nn) ? expf(v - mx) : 0.f;
        float s  = bredSum(e, s_red);
        if (tid < Nn) s_ww[tid] = e / s;
        v  = (tid < Nn) ? rw0[tid] : -3.4e38f;
        mx = bredMax(v, s_red);
        e  = (tid < Nn) ? expf(v - mx) : 0.f;
        s  = bredSum(e, s_red);
        if (tid < Nn) s_rw[tid] = e / s;
    }

    for (int t = 0; t < Tt; t++){
        // prefetch x_t half of the P1 A-tile (no dependency on rd)
        const float4* x4 = (const float4*)x;
        const int i0 = tid, i1 = tid + 512;
        const int r0i = i0 >> 5, q0i = i0 & 31;
        const int r1i = i1 >> 5, q1i = i1 & 31;
        float4 xp0 = __ldcg(&x4[(t*Bb + RB1*32 + r0i)*32 + q0i]);
        float4 xp1 = __ldcg(&x4[(t*Bb + RB1*32 + r1i)*32 + q1i]);

        gbar(grp);   // prev-step rd (group-local) visible

        // ================= P1: ht = tanh([x_t, rd] @ Wc + bc) =================
        {
            const float4* rd4 = (const float4*)g_rd;
            *(float4*)&s_buf[r0i*SAS1 + q0i*4] = xp0;
            *(float4*)&s_buf[r1i*SAS1 + q1i*4] = xp1;
            float4 rv0 = __ldcg(&rd4[(RB1*32 + r0i)*32 + q0i]);
            float4 rv1 = __ldcg(&rd4[(RB1*32 + r1i)*32 + q1i]);
            *(float4*)&s_buf[r0i*SAS1 + 128 + q0i*4] = rv0;
            *(float4*)&s_buf[r1i*SAS1 + 128 + q1i*4] = rv1;
            __syncthreads();

            ull A00=0ull, A01=0ull, A10=0ull, A11=0ull;
            {
                const float* a0p = s_buf + (rp1*2)*SAS1 + ks1*64;
                const float* a1p = a0p + SAS1;
                const ulonglong2* wp = ((const ulonglong2*)Wc) + (ks1*64)*256 + c4g1;
                #pragma unroll 2
                for (int kq = 0; kq < 16; kq++){
                    float4 a0 = *(const float4*)(a0p + 4*kq);
                    float4 a1 = *(const float4*)(a1p + 4*kq);
                    float a0v[4] = {a0.x, a0.y, a0.z, a0.w};
                    float a1v[4] = {a1.x, a1.y, a1.z, a1.w};
                    #pragma unroll
                    for (int j = 0; j < 4; j++){
                        ulonglong2 w = __ldg(&wp[(4*kq + j)*256]);
                        ull p0 = pk2(a0v[j]), p1 = pk2(a1v[j]);
                        f2fma(A00, p0, w.x); f2fma(A01, p0, w.y);
                        f2fma(A10, p1, w.x); f2fma(A11, p1, w.y);
                    }
                }
            }

            // out[t-1] = rd_{t-1} @ Wo + bo : rd lives at A-tile cols 128..255
            if (t > 0 && tid < 128){
                int r = tid >> 2, c = tid & 3;
                int col = CB1*4 + c;
                const float4* ap = (const float4*)(s_buf + r*SAS1 + 128);
                const float4* wt = (const float4*)(g_Wot + col*Mm);
                float4 s4 = make_float4(0,0,0,0);
                #pragma unroll 8
                for (int m = 0; m < 32; m++){
                    float4 av = ap[m];
                    float4 wv = __ldg(&wt[m]);
                    s4.x += av.x*wv.x; s4.y += av.y*wv.y;
                    s4.z += av.z*wv.z; s4.w += av.w*wv.w;
                }
                out[(t-1)*(Bb*Ii) + (RB1*32 + r)*Ii + col] =
                    (s4.x + s4.y) + (s4.z + s4.w) + bo[col];
            }
            __syncthreads();   // A-tile reads complete

            ull* pp = (ull*)s_buf;
            if (ks1 > 0){
                int base = ((ks1-1)*128 + t7)*4;
                pp[base]=A00; pp[base+1]=A01; pp[base+2]=A10; pp[base+3]=A11;
            }
            __syncthreads();
            if (ks1 == 0){
                #pragma unroll
                for (int gg = 0; gg < 3; gg++){
                    int base = (gg*128 + t7)*4;
                    A00 = ad2(A00, pp[base]);   A01 = ad2(A01, pp[base+1]);
                    A10 = ad2(A10, pp[base+2]); A11 = ad2(A11, pp[base+3]);
                }
                float2 v00 = up2(A00), v01 = up2(A01), v10 = up2(A10), v11 = up2(A11);
                float4 bi = __ldg(((const float4*)bc) + c4g1);
                float4 o0 = make_float4(tanhf(v00.x+bi.x), tanhf(v00.y+bi.y),
                                        tanhf(v01.x+bi.z), tanhf(v01.y+bi.w));
                float4 o1 = make_float4(tanhf(v10.x+bi.x), tanhf(v10.y+bi.y),
                                        tanhf(v11.x+bi.z), tanhf(v11.y+bi.w));
                int row = RB1*32 + rp1*2;
                __stcg(((float4*)g_ht) + row*256 + c4g1,     o0);
                __stcg(((float4*)g_ht) + (row+1)*256 + c4g1, o1);
            }
        }
        gbar(grp);   // ht ready

        // ===== P2: [k_w|k_r|erase|add] = act(ht @ W + b), k=1024 k-split 8 =====
        {
            ull A00=0ull, A01=0ull, A10=0ull, A11=0ull;
            const float4* ht4 = (const float4*)g_ht;
            for (int ch = 0; ch < 2; ch++){
                __syncthreads();
                for (int i = tid; i < 2048; i += NTHR){
                    int r = i >> 7, q = i & 127;
                    float4 v = __ldcg(&ht4[(RB2*16 + r)*256 + ch*128 + q]);
                    *(float4*)&s_buf[r*SAS2 + q*4] = v;
                }
                __syncthreads();
                const float* a0p = s_buf + (rp2*2)*SAS2 + g4*64;
                const float* a1p = a0p + SAS2;
                const ulonglong2* wp = ((const ulonglong2*)Wp2) + (ch*512 + g4*64)*32 + c4s;
                #pragma unroll 2
                for (int kq = 0; kq < 16; kq++){
                    float4 a0 = *(const float4*)(a0p + 4*kq);
                    float4 a1 = *(const float4*)(a1p + 4*kq);
                    float a0v[4] = {a0.x, a0.y, a0.z, a0.w};
                    float a1v[4] = {a1.x, a1.y, a1.z, a1.w};
                    #pragma unroll
                    for (int j = 0; j < 4; j++){
                        ulonglong2 w = __ldg(&wp[(4*kq + j)*32]);
                        ull p0 = pk2(a0v[j]), p1 = pk2(a1v[j]);
                        f2fma(A00, p0, w.x); f2fma(A01, p0, w.y);
                        f2fma(A10, p1, w.x); f2fma(A11, p1, w.y);
                    }
                }
            }
            __syncthreads();
            ull* pp = (ull*)s_buf;
            if (g4 > 0){
                int base = ((g4-1)*64 + t6)*4;
                pp[base]=A00; pp[base+1]=A01; pp[base+2]=A10; pp[base+3]=A11;
            }
            __syncthreads();
            if (g4 == 0){
                #pragma unroll
                for (int gg = 0; gg < 7; gg++){
                    int base = (gg*64 + t6)*4;
                    A00 = ad2(A00, pp[base]);   A01 = ad2(A01, pp[base+1]);
                    A10 = ad2(A10, pp[base+2]); A11 = ad2(A11, pp[base+3]);
                }
                float2 v00 = up2(A00), v01 = up2(A01), v10 = up2(A10), v11 = up2(A11);
                float4 bi = __ldg(((const float4*)bp2) + c4s);
                float4 o0, o1;
                if (seg < 2){
                    o0 = make_float4(fmaxf(v00.x+bi.x,0.f), fmaxf(v00.y+bi.y,0.f),
                                     fmaxf(v01.x+bi.z,0.f), fmaxf(v01.y+bi.w,0.f));
                    o1 = make_float4(fmaxf(v10.x+bi.x,0.f), fmaxf(v10.y+bi.y,0.f),
                                     fmaxf(v11.x+bi.z,0.f), fmaxf(v11.y+bi.w,0.f));
                } else {
                    o0 = make_float4(sigmoidf_(v00.x+bi.x), sigmoidf_(v00.y+bi.y),
                                     sigmoidf_(v01.x+bi.z), sigmoidf_(v01.y+bi.w));
                    o1 = make_float4(sigmoidf_(v10.x+bi.x), sigmoidf_(v10.y+bi.y),
                                     sigmoidf_(v11.x+bi.z), sigmoidf_(v11.y+bi.w));
                }
                int row = RB2*16 + rp2*2;
                __stcg(((float4*)op2) + row*32 + c4s,     o0);
                __stcg(((float4*)op2) + (row+1)*32 + c4s, o1);
            }
        }
        gbar(grp);   // k / e / a ready

        // ===== P3 (CTA b): smalls + content addressing + gate/shift/sharpen =====
        {
            // stage ht[b] (4KB) + k/e/a into smem
            if (tid < 256)
                ((float4*)s_ht)[tid] = __ldcg(((const float4*)g_ht) + b*256 + tid);
            if (tid < 128){
                s_kw[tid] = __ldcg(&g_k[b*Mm + tid]);
                s_kr[tid] = __ldcg(&g_k[Bb*Mm + b*Mm + tid]);
                s_e[tid]  = __ldcg(&g_e[b*Mm + tid]);
                s_a[tid]  = __ldcg(&g_a[b*Mm + tid]);
            }
            __syncthreads();
            // 12 small projections from the smem ht stage
            if (wid < 12){
                int c = wid;
                int hd = c / 6, cc = c % 6;
                const float* wp; float bi; int stride;
                if      (cc == 0){ wp = Wb   + hd*Hh;            bi = bb[hd];          stride = 1; }
                else if (cc == 1){ wp = Wg   + hd*Hh;            bi = bg[hd];          stride = 1; }
                else if (cc == 2){ wp = Wgam + hd*Hh;            bi = bgam[hd];        stride = 1; }
                else             { wp = Ws   + hd*Hh*3 + (cc-3); bi = bs[hd*3 + cc-3]; stride = 3; }
                float acc = 0.f;
                #pragma unroll 8
                for (int h = lane; h < Hh; h += 32)
                    acc += s_ht[h] * __ldg(&wp[h*stride]);
                #pragma unroll
                for (int off = 16; off; off >>= 1) acc += __shfl_xor_sync(0xffffffffu, acc, off);
                if (lane == 0) s_sm[c] = acc + bi;
            }
            // key norms
            {
                float v  = (tid < 128) ? s_kw[tid] : ((tid < 256) ? s_kr[tid - 128] : 0.f);
                float sq = v * v;
                #pragma unroll
                for (int off = 16; off; off >>= 1) sq += __shfl_xor_sync(0xffffffffu, sq, off);
                if (lane == 0) s_red[wid] = sq;
                __syncthreads();
                if (tid == 0){
                    s_red[32] = fmaxf(sqrtf(s_red[0]+s_red[1]+s_red[2]+s_red[3]), EPSf);
                    s_red[33] = fmaxf(sqrtf(s_red[4]+s_red[5]+s_red[6]+s_red[7]), EPSf);
                }
                __syncthreads();
            }
            const float ibw = softplusf(s_sm[0]) / s_red[32];
            const float ibr = softplusf(s_sm[6]) / s_red[33];
            __syncthreads();
            // cosine for both heads (norms precomputed in P4/init): 16 warps x 16 rows
            {
                const float4* m4  = ((const float4*)g_mem) + b * (Nn*Mm/4);
                const float4  kw4 = ((float4*)s_kw)[lane];
                const float4  kr4 = ((float4*)s_kr)[lane];
                #pragma unroll 2
                for (int j = 0; j < 16; j += 2){
                    int n0 = wid*16 + j, n1 = n0 + 1;
                    float4 m0 = __ldcg(&m4[n0*32 + lane]);
                    float4 m1 = __ldcg(&m4[n1*32 + lane]);
                    float dw0 = m0.x*kw4.x + m0.y*kw4.y + m0.z*kw4.z + m0.w*kw4.w;
                    float dr0 = m0.x*kr4.x + m0.y*kr4.y + m0.z*kr4.z + m0.w*kr4.w;
                    float dw1 = m1.x*kw4.x + m1.y*kw4.y + m1.z*kw4.z + m1.w*kw4.w;
                    float dr1 = m1.x*kr4.x + m1.y*kr4.y + m1.z*kr4.z + m1.w*kr4.w;
                    #pragma unroll
                    for (int off = 16; off; off >>= 1){
                        dw0 += __shfl_xor_sync(0xffffffffu, dw0, off);
                        dw1 += __shfl_xor_sync(0xffffffffu, dw1, off);
                        dr0 += __shfl_xor_sync(0xffffffffu, dr0, off);
                        dr1 += __shfl_xor_sync(0xffffffffu, dr1, off);
                    }
                    if (lane == 0){
                        s_zw[n0] = dw0 * ibw * s_nrm[n0];  s_zw[n1] = dw1 * ibw * s_nrm[n1];
                        s_zr[n0] = dr0 * ibr * s_nrm[n0];  s_zr[n1] = dr1 * ibr * s_nrm[n1];
                    }
                }
                __syncthreads();
            }
            // two-head weight pipeline IN PARALLEL: half 0 = write head, half 1 = read head
            {
                const int half = tid >> 8, idx = tid & 255;
                float* szH    = half ? s_zr : s_zw;
                float* sprevH = half ? s_rw : s_ww;
                float* s_tmpH = s_tmp + half*256;
                float graw = s_sm[half*6 + 1];
                float gamr = s_sm[half*6 + 2];
                float r0s  = s_sm[half*6 + 3], r1s = s_sm[half*6 + 4], r2s = s_sm[half*6 + 5];
                float z   = szH[idx];
                float mx  = hredMax(z, s_red);
                float ez  = expf(z - mx);
                float smv = hredSum(ez, s_red);
                float wc  = ez / smv;
                float g   = sigmoidf_(graw);
                s_tmpH[idx] = g*wc + (1.f - g)*sprevH[idx];
                __syncthreads();
                float m3 = fmaxf(r0s, fmaxf(r1s, r2s));
                float e0 = expf(r0s - m3), e1 = expf(r1s - m3), e2 = expf(r2s - m3);
                float i3 = 1.f / (e0 + e1 + e2);
                float wsh = e0*i3 * s_tmpH[(idx + 255) & 255]
                          + e1*i3 * s_tmpH[idx]
                          + e2*i3 * s_tmpH[(idx + 1) & 255];
                float gamma = fmaxf(gamr, 0.f) + 1.f;
                float wpow  = powf(wsh, gamma);
                float tsum  = hredSum(wpow, s_red);
                sprevH[idx] = wpow / tsum;
                __syncthreads();
            }
        }

        // ===== P4 (CTA b): memory update + rd + next-step inverse norms =====
        {
            const int mq    = tid & 31;
            const int rbase = tid >> 5;      // 0..15
            const float4 e4 = ((float4*)s_e)[mq];
            const float4 a4 = ((float4*)s_a)[mq];
            float4* m4 = ((float4*)g_mem) + b * (Nn*Mm/4);
            float4 prd = make_float4(0,0,0,0);
            #pragma unroll 4
            for (int it = 0; it < 16; it++){
                int n = it*16 + rbase;
                float wwn = s_ww[n], rwn = s_rw[n];
                float4 mv = __ldcg((const float4*)&m4[n*32 + mq]);
                float4 nv;
                nv.x = mv.x*(1.f - wwn*e4.x) + wwn*a4.x;
                nv.y = mv.y*(1.f - wwn*e4.y) + wwn*a4.y;
                nv.z = mv.z*(1.f - wwn*e4.z) + wwn*a4.z;
                nv.w = mv.w*(1.f - wwn*e4.w) + wwn*a4.w;
                __stcg(&m4[n*32 + mq], nv);
                prd.x += rwn*nv.x; prd.y += rwn*nv.y; prd.z += rwn*nv.z; prd.w += rwn*nv.w;
                float nn = nv.x*nv.x + nv.y*nv.y + nv.z*nv.z + nv.w*nv.w;
                #pragma unroll
                for (int off = 16; off; off >>= 1) nn += __shfl_xor_sync(0xffffffffu, nn, off);
                if (mq == 0) s_nrm[n] = 1.f / fmaxf(sqrtf(nn), EPSf);
            }
            s_prd[tid] = prd;
            __syncthreads();
            if (tid < 32){
                float4 r = s_prd[tid];
                #pragma unroll
                for (int j = 1; j < 16; j++){
                    float4 v = s_prd[tid + 32*j];
                    r.x += v.x; r.y += v.y; r.z += v.z; r.w += v.w;
                }
                __stcg(((float4*)g_rd) + b*32 + tid, r);
            }
        }
    }

    // ===== tail: out[63] = rd_63 @ Wo + bo =====
    gbar(grp);
    if (tid < 128){
        int r = tid >> 2, c = tid & 3;
        int row = RB1*32 + r, col = CB1*4 + c;
        const float4* wt = (const float4*)(g_Wot + col*Mm);
        const float4* rp = ((const float4*)g_rd) + row*32;
        float4 s4 = make_float4(0,0,0,0);
        #pragma unroll 8
        for (int m = 0; m < 32; m++){
            float4 av = __ldcg(&rp[m]);
            float4 wv = __ldg(&wt[m]);
            s4.x += av.x*wv.x; s4.y += av.y*wv.y;
            s4.z += av.z*wv.z; s4.w += av.w*wv.w;
        }
        out[63*(Bb*Ii) + row*Ii + col] = (s4.x + s4.y) + (s4.z + s4.w) + bo[col];
    }
}

extern "C" void kernel_launch(void* const* d_in, const int* in_sizes, int n_in,
                              void* d_out, int out_size){
    (void)in_sizes; (void)n_in; (void)out_size;
    static int configured = 0;
    if (!configured){
        cudaFuncSetAttribute(ntm_kernel, cudaFuncAttributeMaxDynamicSharedMemorySize,
                             SBUF * (int)sizeof(float));
        configured = 1;
    }
    ntm_kernel<<<NCTA, NTHR, SBUF * sizeof(float)>>>(
        (const float*)d_in[0],  (const float*)d_in[1],  (const float*)d_in[2],
        (const float*)d_in[3],  (const float*)d_in[4],  (const float*)d_in[5],
        (const float*)d_in[6],  (const float*)d_in[7],  (const float*)d_in[8],
        (const float*)d_in[9],  (const float*)d_in[10], (const float*)d_in[11],
        (const float*)d_in[12], (const float*)d_in[13], (const float*)d_in[14],
        (const float*)d_in[15], (const float*)d_in[16], (const float*)d_in[17],
        (const float*)d_in[18], (const float*)d_in[19], (const float*)d_in[20],
        (const float*)d_in[21], (const float*)d_in[22],
        (float*)d_out);
}

// round 17
// speedup vs baseline: 1.0781x; 1.0781x over previous
#include <cuda_runtime.h>
#include <math.h>

#define Tt 64
#define Bb 256
#define Nn 256
#define Mm 128
#define Hh 1024
#define Ii 128
#define EPSf 1e-8f
#define NCTA 256
#define NTHR 512

typedef unsigned long long ull;

#define SBUF 8448      // floats: stage buffer + P3/P4 scratch
#define SMEMRES 16384  // floats: resident memory rows 0..127 (64KB)
#define SMEMF (SBUF + SMEMRES)
#define SAS1 260       // P1 A row stride
#define SAS2 516       // P2 A row stride

// ---------------- persistent device scratch ----------------
__device__ __align__(16) float g_mem[Bb*Nn*Mm];   // rows 128..255 used; L2-resident
__device__ __align__(16) float g_ht [Bb*Hh];
__device__ __align__(16) float g_k  [2*Bb*Mm];
__device__ __align__(16) float g_e  [Bb*Mm];
__device__ __align__(16) float g_a  [Bb*Mm];
__device__ __align__(16) float g_rd [Bb*Mm];
__device__ __align__(16) float g_Wot[Ii*Mm];      // Wo^T [col][m]
__device__ unsigned g_cnt[8*32];
__device__ unsigned g_gen[8*32];

// ---------------- f32x2 packed math ----------------
__device__ __forceinline__ ull pk2(float a){
    ull r; asm("mov.b64 %0,{%1,%1};" : "=l"(r) : "f"(a)); return r;
}
__device__ __forceinline__ void f2fma(ull& c, ull a, ull b){
    asm("fma.rn.f32x2 %0,%1,%2,%0;" : "+l"(c) : "l"(a), "l"(b));
}
__device__ __forceinline__ ull ad2(ull a, ull b){
    ull r; asm("add.rn.f32x2 %0,%1,%2;" : "=l"(r) : "l"(a), "l"(b)); return r;
}
__device__ __forceinline__ float2 up2(ull v){
    float2 f; asm("mov.b64 {%0,%1},%2;" : "=f"(f.x), "=f"(f.y) : "l"(v)); return f;
}

// ---------------- group barrier (32 CTAs; all deps group-local) ----------------
__device__ __forceinline__ void gbar(int grp){
    __threadfence();
    __syncthreads();
    if (threadIdx.x == 0){
        volatile unsigned* genp = &g_gen[grp*32];
        unsigned cur = *genp;
        if (atomicAdd(&g_cnt[grp*32], 1u) == 31u){
            g_cnt[grp*32] = 0u;
            __threadfence();
            *genp = cur + 1u;
        } else {
            while (*genp == cur) { __nanosleep(32); }
        }
        __threadfence();
    }
    __syncthreads();
}

// ---------------- full-block reductions (512 thr), init only ----------------
__device__ __forceinline__ float bredSum(float v, float* s_red){
    int lane = threadIdx.x & 31, wid = threadIdx.x >> 5;
    #pragma unroll
    for (int off = 16; off; off >>= 1) v += __shfl_xor_sync(0xffffffffu, v, off);
    if (lane == 0) s_red[wid] = v;
    __syncthreads();
    if (threadIdx.x == 0){
        float s = 0.f;
        #pragma unroll
        for (int j = 0; j < 16; j++) s += s_red[j];
        s_red[32] = s;
    }
    __syncthreads();
    return s_red[32];
}
__device__ __forceinline__ float bredMax(float v, float* s_red){
    int lane = threadIdx.x & 31, wid = threadIdx.x >> 5;
    #pragma unroll
    for (int off = 16; off; off >>= 1) v = fmaxf(v, __shfl_xor_sync(0xffffffffu, v, off));
    if (lane == 0) s_red[wid] = v;
    __syncthreads();
    if (threadIdx.x == 0){
        float s = -3.4e38f;
        #pragma unroll
        for (int j = 0; j < 16; j++) s = fmaxf(s, s_red[j]);
        s_red[32] = s;
    }
    __syncthreads();
    return s_red[32];
}

// ---------------- half-block reductions (256 thr per half, parallel heads) ----------------
__device__ __forceinline__ float hredSum(float v, float* s_red){
    int tid = threadIdx.x;
    int lane = tid & 31, wid = tid >> 5, half = tid >> 8;
    #pragma unroll
    for (int off = 16; off; off >>= 1) v += __shfl_xor_sync(0xffffffffu, v, off);
    if (lane == 0) s_red[wid] = v;
    __syncthreads();
    if ((tid & 255) == 0){
        float s = 0.f;
        #pragma unroll
        for (int j = 0; j < 8; j++) s += s_red[(half<<3) + j];
        s_red[32 + half] = s;
    }
    __syncthreads();
    return s_red[32 + half];
}
__device__ __forceinline__ float hredMax(float v, float* s_red){
    int tid = threadIdx.x;
    int lane = tid & 31, wid = tid >> 5, half = tid >> 8;
    #pragma unroll
    for (int off = 16; off; off >>= 1) v = fmaxf(v, __shfl_xor_sync(0xffffffffu, v, off));
    if (lane == 0) s_red[wid] = v;
    __syncthreads();
    if ((tid & 255) == 0){
        float s = -3.4e38f;
        #pragma unroll
        for (int j = 0; j < 8; j++) s = fmaxf(s, s_red[(half<<3) + j]);
        s_red[32 + half] = s;
    }
    __syncthreads();
    return s_red[32 + half];
}

__device__ __forceinline__ float softplusf(float x){
    return fmaxf(x, 0.f) + log1pf(expf(-fabsf(x)));
}
__device__ __forceinline__ float sigmoidf_(float x){
    return 1.f / (1.f + expf(-x));
}

// ---------------- the persistent NTM kernel ----------------
__global__ void __launch_bounds__(NTHR, 2) ntm_kernel(
    const float* __restrict__ x,
    const float* __restrict__ Wc,   const float* __restrict__ bc,
    const float* __restrict__ Wk,   const float* __restrict__ bk,
    const float* __restrict__ Wb,   const float* __restrict__ bb,
    const float* __restrict__ Wg,   const float* __restrict__ bg,
    const float* __restrict__ Ws,   const float* __restrict__ bs,
    const float* __restrict__ Wgam, const float* __restrict__ bgam,
    const float* __restrict__ We,   const float* __restrict__ be,
    const float* __restrict__ Wa,   const float* __restrict__ ba,
    const float* __restrict__ Wo,   const float* __restrict__ bo,
    const float* __restrict__ memory0,
    const float* __restrict__ ww0,  const float* __restrict__ rw0,
    const float* __restrict__ read0,
    float* __restrict__ out)
{
    extern __shared__ __align__(16) float s_buf[];
    float4* s_mem4 = (float4*)(s_buf + SBUF);   // resident memory rows 0..127

    __shared__ float s_ww[Nn];
    __shared__ float s_rw[Nn];
    __shared__ float s_red[40];
    __shared__ float s_sm[16];

    const int tid  = threadIdx.x;
    const int cta  = blockIdx.x;
    const int b    = cta;
    const int grp  = cta >> 5;
    const int wid  = tid >> 5, lane = tid & 31;

    // ---- P1: 8 RB(32 rows) x 32 CB(32 cols) over [256,1024], k=256, k-split 4 ----
    const int RB1 = cta >> 5, CB1 = cta & 31;
    const int ks1 = tid >> 7, t7 = tid & 127;
    const int rp1 = t7 >> 3, cq1 = t7 & 7;
    const int c4g1 = CB1*8 + cq1;
    // ---- P2: 16 RB(16 rows) x 16 CB(32 cols) over [256,512], k=1024, k-split 8 ----
    const int RB2 = cta >> 4, CB2 = cta & 15;
    const int seg = CB2 >> 2;
    const int g4 = tid >> 6, t6 = tid & 63;
    const int rp2 = t6 >> 3, cq2 = t6 & 7;
    const int c4s = (CB2 & 3)*8 + cq2;
    const float *Wp2, *bp2; float *op2;
    if      (seg == 0){ Wp2 = Wk;          bp2 = bk;      op2 = g_k; }
    else if (seg == 1){ Wp2 = Wk + Hh*Mm;  bp2 = bk + Mm; op2 = g_k + Bb*Mm; }
    else if (seg == 2){ Wp2 = We;          bp2 = be;      op2 = g_e; }
    else              { Wp2 = Wa;          bp2 = ba;      op2 = g_a; }

    // P3/P4 scratch carve inside s_buf
    float*  s_kw  = s_buf;                 // 128
    float*  s_kr  = s_buf + 128;           // 128
    float*  s_e   = s_buf + 256;           // 128
    float*  s_a   = s_buf + 384;           // 128
    float*  s_zw  = s_buf + 512;           // 256
    float*  s_zr  = s_buf + 768;           // 256
    float*  s_tmp = s_buf + 1024;          // 512 (two head buffers)
    float4* s_prd = (float4*)(s_buf + 1536); // 512 f4

    // ---------------- init ----------------
    {
        {
            int col = CB1*4 + (tid >> 7), m = tid & 127;
            g_Wot[col*Mm + m] = Wo[m*Ii + col];
        }
        const float4* ms = (const float4*)memory0;
        // rows 0..127 -> smem resident; rows 128..255 -> g_mem
        for (int i = tid; i < SMEMRES/4; i += NTHR) s_mem4[i] = ms[i];
        float4* md = ((float4*)g_mem) + b * (Nn*Mm/4);
        for (int i = SMEMRES/4 + tid; i < Nn*Mm/4; i += NTHR) md[i] = ms[i];
        if (tid < Mm) __stcg(&g_rd[b*Mm + tid], read0[tid]);
        float v  = (tid < Nn) ? ww0[tid] : -3.4e38f;
        float mx = bredMax(v, s_red);
        float e  = (tid < Nn) ? expf(v - mx) : 0.f;
        float s  = bredSum(e, s_red);
        if (tid < Nn) s_ww[tid] = e / s;
        v  = (tid < Nn) ? rw0[tid] : -3.4e38f;
        mx = bredMax(v, s_red);
        e  = (tid < Nn) ? expf(v - mx) : 0.f;
        s  = bredSum(e, s_red);
        if (tid < Nn) s_rw[tid] = e / s;
    }

    for (int t = 0; t < Tt; t++){
        // prefetch x_t half of the P1 A-tile (no dependency on rd)
        const float4* x4 = (const float4*)x;
        const int i0 = tid, i1 = tid + 512;
        const int r0i = i0 >> 5, q0i = i0 & 31;
        const int r1i = i1 >> 5, q1i = i1 & 31;
        float4 xp0 = x4[(t*Bb + RB1*32 + r0i)*32 + q0i];
        float4 xp1 = x4[(t*Bb + RB1*32 + r1i)*32 + q1i];

        gbar(grp);   // prev-step rd (group-local) visible

        // ================= P1: ht = tanh([x_t, rd] @ Wc + bc) =================
        {
            const float4* rd4 = (const float4*)g_rd;
            *(float4*)&s_buf[r0i*SAS1 + q0i*4] = xp0;
            *(float4*)&s_buf[r1i*SAS1 + q1i*4] = xp1;
            float4 rv0 = __ldcg(&rd4[(RB1*32 + r0i)*32 + q0i]);
            float4 rv1 = __ldcg(&rd4[(RB1*32 + r1i)*32 + q1i]);
            *(float4*)&s_buf[r0i*SAS1 + 128 + q0i*4] = rv0;
            *(float4*)&s_buf[r1i*SAS1 + 128 + q1i*4] = rv1;
            __syncthreads();

            ull A00=0ull, A01=0ull, A10=0ull, A11=0ull;
            {
                const float* a0p = s_buf + (rp1*2)*SAS1 + ks1*64;
                const float* a1p = a0p + SAS1;
                const ulonglong2* wp = ((const ulonglong2*)Wc) + (ks1*64)*256 + c4g1;
                #pragma unroll 2
                for (int kq = 0; kq < 16; kq++){
                    float4 a0 = *(const float4*)(a0p + 4*kq);
                    float4 a1 = *(const float4*)(a1p + 4*kq);
                    float a0v[4] = {a0.x, a0.y, a0.z, a0.w};
                    float a1v[4] = {a1.x, a1.y, a1.z, a1.w};
                    #pragma unroll
                    for (int j = 0; j < 4; j++){
                        ulonglong2 w = __ldg(&wp[(4*kq + j)*256]);
                        ull p0 = pk2(a0v[j]), p1 = pk2(a1v[j]);
                        f2fma(A00, p0, w.x); f2fma(A01, p0, w.y);
                        f2fma(A10, p1, w.x); f2fma(A11, p1, w.y);
                    }
                }
            }

            // out[t-1] = rd_{t-1} @ Wo + bo : rd lives at A-tile cols 128..255
            if (t > 0 && tid < 128){
                int r = tid >> 2, c = tid & 3;
                int col = CB1*4 + c;
                const float4* ap = (const float4*)(s_buf + r*SAS1 + 128);
                const float4* wt = (const float4*)(g_Wot + col*Mm);
                float4 s4 = make_float4(0,0,0,0);
                #pragma unroll 8
                for (int m = 0; m < 32; m++){
                    float4 av = ap[m];
                    float4 wv = __ldg(&wt[m]);
                    s4.x += av.x*wv.x; s4.y += av.y*wv.y;
                    s4.z += av.z*wv.z; s4.w += av.w*wv.w;
                }
                out[(t-1)*(Bb*Ii) + (RB1*32 + r)*Ii + col] =
                    (s4.x + s4.y) + (s4.z + s4.w) + bo[col];
            }
            __syncthreads();   // A-tile reads complete

            ull* pp = (ull*)s_buf;
            if (ks1 > 0){
                int base = ((ks1-1)*128 + t7)*4;
                pp[base]=A00; pp[base+1]=A01; pp[base+2]=A10; pp[base+3]=A11;
            }
            __syncthreads();
            if (ks1 == 0){
                #pragma unroll
                for (int gg = 0; gg < 3; gg++){
                    int base = (gg*128 + t7)*4;
                    A00 = ad2(A00, pp[base]);   A01 = ad2(A01, pp[base+1]);
                    A10 = ad2(A10, pp[base+2]); A11 = ad2(A11, pp[base+3]);
                }
                float2 v00 = up2(A00), v01 = up2(A01), v10 = up2(A10), v11 = up2(A11);
                float4 bi = __ldg(((const float4*)bc) + c4g1);
                float4 o0 = make_float4(tanhf(v00.x+bi.x), tanhf(v00.y+bi.y),
                                        tanhf(v01.x+bi.z), tanhf(v01.y+bi.w));
                float4 o1 = make_float4(tanhf(v10.x+bi.x), tanhf(v10.y+bi.y),
                                        tanhf(v11.x+bi.z), tanhf(v11.y+bi.w));
                int row = RB1*32 + rp1*2;
                __stcg(((float4*)g_ht) + row*256 + c4g1,     o0);
                __stcg(((float4*)g_ht) + (row+1)*256 + c4g1, o1);
            }
        }
        gbar(grp);   // ht ready

        // ===== P2: [k_w|k_r|erase|add] = act(ht @ W + b), k=1024 k-split 8 =====
        {
            ull A00=0ull, A01=0ull, A10=0ull, A11=0ull;
            const float4* ht4 = (const float4*)g_ht;
            for (int ch = 0; ch < 2; ch++){
                __syncthreads();
                for (int i = tid; i < 2048; i += NTHR){
                    int r = i >> 7, q = i & 127;
                    float4 v = __ldcg(&ht4[(RB2*16 + r)*256 + ch*128 + q]);
                    *(float4*)&s_buf[r*SAS2 + q*4] = v;
                }
                __syncthreads();
                const float* a0p = s_buf + (rp2*2)*SAS2 + g4*64;
                const float* a1p = a0p + SAS2;
                const ulonglong2* wp = ((const ulonglong2*)Wp2) + (ch*512 + g4*64)*32 + c4s;
                #pragma unroll 2
                for (int kq = 0; kq < 16; kq++){
                    float4 a0 = *(const float4*)(a0p + 4*kq);
                    float4 a1 = *(const float4*)(a1p + 4*kq);
                    float a0v[4] = {a0.x, a0.y, a0.z, a0.w};
                    float a1v[4] = {a1.x, a1.y, a1.z, a1.w};
                    #pragma unroll
                    for (int j = 0; j < 4; j++){
                        ulonglong2 w = __ldg(&wp[(4*kq + j)*32]);
                        ull p0 = pk2(a0v[j]), p1 = pk2(a1v[j]);
                        f2fma(A00, p0, w.x); f2fma(A01, p0, w.y);
                        f2fma(A10, p1, w.x); f2fma(A11, p1, w.y);
                    }
                }
            }
            __syncthreads();
            ull* pp = (ull*)s_buf;
            if (g4 > 0){
                int base = ((g4-1)*64 + t6)*4;
                pp[base]=A00; pp[base+1]=A01; pp[base+2]=A10; pp[base+3]=A11;
            }
            __syncthreads();
            if (g4 == 0){
                #pragma unroll
                for (int gg = 0; gg < 7; gg++){
                    int base = (gg*64 + t6)*4;
                    A00 = ad2(A00, pp[base]);   A01 = ad2(A01, pp[base+1]);
                    A10 = ad2(A10, pp[base+2]); A11 = ad2(A11, pp[base+3]);
                }
                float2 v00 = up2(A00), v01 = up2(A01), v10 = up2(A10), v11 = up2(A11);
                float4 bi = __ldg(((const float4*)bp2) + c4s);
                float4 o0, o1;
                if (seg < 2){
                    o0 = make_float4(fmaxf(v00.x+bi.x,0.f), fmaxf(v00.y+bi.y,0.f),
                                     fmaxf(v01.x+bi.z,0.f), fmaxf(v01.y+bi.w,0.f));
                    o1 = make_float4(fmaxf(v10.x+bi.x,0.f), fmaxf(v10.y+bi.y,0.f),
                                     fmaxf(v11.x+bi.z,0.f), fmaxf(v11.y+bi.w,0.f));
                } else {
                    o0 = make_float4(sigmoidf_(v00.x+bi.x), sigmoidf_(v00.y+bi.y),
                                     sigmoidf_(v01.x+bi.z), sigmoidf_(v01.y+bi.w));
                    o1 = make_float4(sigmoidf_(v10.x+bi.x), sigmoidf_(v10.y+bi.y),
                                     sigmoidf_(v11.x+bi.z), sigmoidf_(v11.y+bi.w));
                }
                int row = RB2*16 + rp2*2;
                __stcg(((float4*)op2) + row*32 + c4s,     o0);
                __stcg(((float4*)op2) + (row+1)*32 + c4s, o1);
            }
        }
        gbar(grp);   // k / e / a ready

        // ===== P3 (CTA b): smalls + content addressing + gate/shift/sharpen =====
        {
            if (tid < 128){
                s_kw[tid] = __ldcg(&g_k[b*Mm + tid]);
                s_kr[tid] = __ldcg(&g_k[Bb*Mm + b*Mm + tid]);
                s_e[tid]  = __ldcg(&g_e[b*Mm + tid]);
                s_a[tid]  = __ldcg(&g_a[b*Mm + tid]);
            }
            if (wid < 12){
                int c = wid;
                int hd = c / 6, cc = c % 6;
                const float* wp; float bi; int stride;
                if      (cc == 0){ wp = Wb   + hd*Hh;            bi = bb[hd];          stride = 1; }
                else if (cc == 1){ wp = Wg   + hd*Hh;            bi = bg[hd];          stride = 1; }
                else if (cc == 2){ wp = Wgam + hd*Hh;            bi = bgam[hd];        stride = 1; }
                else             { wp = Ws   + hd*Hh*3 + (cc-3); bi = bs[hd*3 + cc-3]; stride = 3; }
                float acc = 0.f;
                #pragma unroll 8
                for (int h = lane; h < Hh; h += 32)
                    acc += __ldcg(&g_ht[b*Hh + h]) * wp[h*stride];
                #pragma unroll
                for (int off = 16; off; off >>= 1) acc += __shfl_xor_sync(0xffffffffu, acc, off);
                if (lane == 0) s_sm[c] = acc + bi;
            }
            __syncthreads();
            // key norms
            {
                float v  = (tid < 128) ? s_kw[tid] : ((tid < 256) ? s_kr[tid - 128] : 0.f);
                float sq = v * v;
                #pragma unroll
                for (int off = 16; off; off >>= 1) sq += __shfl_xor_sync(0xffffffffu, sq, off);
                if (lane == 0) s_red[wid] = sq;
                __syncthreads();
                if (tid == 0){
                    s_red[32] = fmaxf(sqrtf(s_red[0]+s_red[1]+s_red[2]+s_red[3]), EPSf);
                    s_red[33] = fmaxf(sqrtf(s_red[4]+s_red[5]+s_red[6]+s_red[7]), EPSf);
                }
                __syncthreads();
            }
            const float ibw = softplusf(s_sm[0]) / s_red[32];
            const float ibr = softplusf(s_sm[6]) / s_red[33];
            __syncthreads();
            // cosine for both heads: warps 0..7 -> smem rows, 8..15 -> L2 rows
            {
                const float4* mp = (wid < 8)
                    ? (const float4*)s_mem4
                    : (((const float4*)g_mem) + b * (Nn*Mm/4));
                const float4  kw4 = ((float4*)s_kw)[lane];
                const float4  kr4 = ((float4*)s_kr)[lane];
                for (int j = 0; j < 16; j += 2){
                    int n0 = wid*16 + j, n1 = n0 + 1;
                    float4 m0 = mp[n0*32 + lane];
                    float4 m1 = mp[n1*32 + lane];
                    float dw0 = m0.x*kw4.x + m0.y*kw4.y + m0.z*kw4.z + m0.w*kw4.w;
                    float dr0 = m0.x*kr4.x + m0.y*kr4.y + m0.z*kr4.z + m0.w*kr4.w;
                    float nn0 = m0.x*m0.x + m0.y*m0.y + m0.z*m0.z + m0.w*m0.w;
                    float dw1 = m1.x*kw4.x + m1.y*kw4.y + m1.z*kw4.z + m1.w*kw4.w;
                    float dr1 = m1.x*kr4.x + m1.y*kr4.y + m1.z*kr4.z + m1.w*kr4.w;
                    float nn1 = m1.x*m1.x + m1.y*m1.y + m1.z*m1.z + m1.w*m1.w;
                    #pragma unroll
                    for (int off = 16; off; off >>= 1){
                        dw0 += __shfl_xor_sync(0xffffffffu, dw0, off);
                        dw1 += __shfl_xor_sync(0xffffffffu, dw1, off);
                        dr0 += __shfl_xor_sync(0xffffffffu, dr0, off);
                        dr1 += __shfl_xor_sync(0xffffffffu, dr1, off);
                        nn0 += __shfl_xor_sync(0xffffffffu, nn0, off);
                        nn1 += __shfl_xor_sync(0xffffffffu, nn1, off);
                    }
                    if (lane == 0){
                        float i0n = 1.f / fmaxf(sqrtf(nn0), EPSf);
                        float i1n = 1.f / fmaxf(sqrtf(nn1), EPSf);
                        s_zw[n0] = dw0 * ibw * i0n;  s_zw[n1] = dw1 * ibw * i1n;
                        s_zr[n0] = dr0 * ibr * i0n;  s_zr[n1] = dr1 * ibr * i1n;
                    }
                }
                __syncthreads();
            }
            // two-head weight pipeline IN PARALLEL: half 0 = write head, half 1 = read head
            {
                const int half = tid >> 8, idx = tid & 255;
                float* szH    = half ? s_zr : s_zw;
                float* sprevH = half ? s_rw : s_ww;
                float* s_tmpH = s_tmp + half*256;
                float graw = s_sm[half*6 + 1];
                float gamr = s_sm[half*6 + 2];
                float r0s  = s_sm[half*6 + 3], r1s = s_sm[half*6 + 4], r2s = s_sm[half*6 + 5];
                float z   = szH[idx];
                float mx  = hredMax(z, s_red);
                float ez  = expf(z - mx);
                float smv = hredSum(ez, s_red);
                float wc  = ez / smv;
                float g   = sigmoidf_(graw);
                s_tmpH[idx] = g*wc + (1.f - g)*sprevH[idx];
                __syncthreads();
                float m3 = fmaxf(r0s, fmaxf(r1s, r2s));
                float e0 = expf(r0s - m3), e1 = expf(r1s - m3), e2 = expf(r2s - m3);
                float i3 = 1.f / (e0 + e1 + e2);
                float wsh = e0*i3 * s_tmpH[(idx + 255) & 255]
                          + e1*i3 * s_tmpH[idx]
                          + e2*i3 * s_tmpH[(idx + 1) & 255];
                float gamma = fmaxf(gamr, 0.f) + 1.f;
                float wpow  = powf(wsh, gamma);
                float tsum  = hredSum(wpow, s_red);
                sprevH[idx] = wpow / tsum;
                __syncthreads();
            }
        }

        // ===== P4 (CTA b): memory update + rd (rows 0..127 in smem, 128..255 in L2) =====
        {
            const int mq    = tid & 31;
            const int rbase = tid >> 5;      // 0..15
            const float4 e4 = ((float4*)s_e)[mq];
            const float4 a4 = ((float4*)s_a)[mq];
            float4* m4g = ((float4*)g_mem) + b * (Nn*Mm/4);
            float4 prd = make_float4(0,0,0,0);
            #pragma unroll 4
            for (int it = 0; it < 16; it++){
                int n = it*16 + rbase;
                float4* tgt = (it < 8) ? (s_mem4 + n*32 + mq) : (m4g + n*32 + mq);
                float wwn = s_ww[n], rwn = s_rw[n];
                float4 mv = *tgt;
                float4 nv;
                nv.x = mv.x*(1.f - wwn*e4.x) + wwn*a4.x;
                nv.y = mv.y*(1.f - wwn*e4.y) + wwn*a4.y;
                nv.z = mv.z*(1.f - wwn*e4.z) + wwn*a4.z;
                nv.w = mv.w*(1.f - wwn*e4.w) + wwn*a4.w;
                *tgt = nv;
                prd.x += rwn*nv.x; prd.y += rwn*nv.y; prd.z += rwn*nv.z; prd.w += rwn*nv.w;
            }
            s_prd[tid] = prd;
            __syncthreads();
            if (tid < 32){
                float4 r = s_prd[tid];
                #pragma unroll
                for (int j = 1; j < 16; j++){
                    float4 v = s_prd[tid + 32*j];
                    r.x += v.x; r.y += v.y; r.z += v.z; r.w += v.w;
                }
                __stcg(((float4*)g_rd) + b*32 + tid, r);
            }
        }
    }

    // ===== tail: out[63] = rd_63 @ Wo + bo =====
    gbar(grp);
    if (tid < 128){
        int r = tid >> 2, c = tid & 3;
        int row = RB1*32 + r, col = CB1*4 + c;
        const float4* wt = (const float4*)(g_Wot + col*Mm);
        const float4* rp = ((const float4*)g_rd) + row*32;
        float4 s4 = make_float4(0,0,0,0);
        #pragma unroll 8
        for (int m = 0; m < 32; m++){
            float4 av = __ldcg(&rp[m]);
            float4 wv = __ldg(&wt[m]);
            s4.x += av.x*wv.x; s4.y += av.y*wv.y;
            s4.z += av.z*wv.z; s4.w += av.w*wv.w;
        }
        out[63*(Bb*Ii) + row*Ii + col] = (s4.x + s4.y) + (s4.z + s4.w) + bo[col];
    }
}

extern "C" void kernel_launch(void* const* d_in, const int* in_sizes, int n_in,
                              void* d_out, int out_size){
    (void)in_sizes; (void)n_in; (void)out_size;
    static int configured = 0;
    if (!configured){
        cudaFuncSetAttribute(ntm_kernel, cudaFuncAttributeMaxDynamicSharedMemorySize,
                             SMEMF * (int)sizeof(float));
        configured = 1;
    }
    ntm_kernel<<<NCTA, NTHR, SMEMF * sizeof(float)>>>(
        (const float*)d_in[0],  (const float*)d_in[1],  (const float*)d_in[2],
        (const float*)d_in[3],  (const float*)d_in[4],  (const float*)d_in[5],
        (const float*)d_in[6],  (const float*)d_in[7],  (const float*)d_in[8],
        (const float*)d_in[9],  (const float*)d_in[10], (const float*)d_in[11],
        (const float*)d_in[12], (const float*)d_in[13], (const float*)d_in[14],
        (const float*)d_in[15], (const float*)d_in[16], (const float*)d_in[17],
        (const float*)d_in[18], (const float*)d_in[19], (const float*)d_in[20],
        (const float*)d_in[21], (const float*)d_in[22],
        (float*)d_out);
}